// round 13
// baseline (speedup 1.0000x reference)
#include <cuda_runtime.h>
#include <cuda_bf16.h>
#include <cstdint>

#define CLA_L     16384
#define CLA_HID   512
#define CLA_QKVN  1536

__device__ int           g_order[CLA_L];
__device__ __nv_bfloat16 g_xb[(size_t)CLA_L * CLA_HID];
__device__ __nv_bfloat16 g_wqkvt[(size_t)CLA_QKVN * CLA_HID];
__device__ __nv_bfloat16 g_woutt[(size_t)CLA_HID * CLA_HID];
__device__ __nv_bfloat16 g_qkvb[(size_t)CLA_L * CLA_QKVN];
__device__ __nv_bfloat16 g_attnb[(size_t)CLA_L * CLA_HID];

// ------------------------- low-level helpers -------------------------------
__device__ __forceinline__ uint32_t s2u(const void* p) {
    return (uint32_t)__cvta_generic_to_shared(p);
}
__device__ __forceinline__ void cp_async16(uint32_t dst, const void* src) {
    asm volatile("cp.async.cg.shared.global [%0], [%1], 16;\n" ::"r"(dst), "l"(src));
}
__device__ __forceinline__ void cp_commit() {
    asm volatile("cp.async.commit_group;\n");
}
template <int N> __device__ __forceinline__ void cp_wait() {
    asm volatile("cp.async.wait_group %0;\n" ::"n"(N));
}
__device__ __forceinline__ void ldsm_x4(unsigned* r, uint32_t a) {
    asm volatile("ldmatrix.sync.aligned.m8n8.x4.shared.b16 {%0,%1,%2,%3}, [%4];\n"
                 : "=r"(r[0]), "=r"(r[1]), "=r"(r[2]), "=r"(r[3]) : "r"(a));
}
__device__ __forceinline__ void ldsm_x4_t(unsigned* r, uint32_t a) {
    asm volatile("ldmatrix.sync.aligned.m8n8.x4.trans.shared.b16 {%0,%1,%2,%3}, [%4];\n"
                 : "=r"(r[0]), "=r"(r[1]), "=r"(r[2]), "=r"(r[3]) : "r"(a));
}
__device__ __forceinline__ void ldsm_x2(unsigned& r0, unsigned& r1, uint32_t a) {
    asm volatile("ldmatrix.sync.aligned.m8n8.x2.shared.b16 {%0,%1}, [%2];\n"
                 : "=r"(r0), "=r"(r1) : "r"(a));
}
__device__ __forceinline__ void mma_bf16(float* c, const unsigned* a,
                                         unsigned b0, unsigned b1) {
    asm volatile(
        "mma.sync.aligned.m16n8k16.row.col.f32.bf16.bf16.f32 "
        "{%0,%1,%2,%3},{%4,%5,%6,%7},{%8,%9},{%0,%1,%2,%3};\n"
        : "+f"(c[0]), "+f"(c[1]), "+f"(c[2]), "+f"(c[3])
        : "r"(a[0]), "r"(a[1]), "r"(a[2]), "r"(a[3]), "r"(b0), "r"(b1));
}
__device__ __forceinline__ float fexp2(float y) {
    y = fmaxf(y, -126.0f);
    float n = rintf(y);
    float f = y - n;
    float p = 1.33335581e-3f;
    p = fmaf(p, f, 9.61812910e-3f);
    p = fmaf(p, f, 5.55041087e-2f);
    p = fmaf(p, f, 2.40226507e-1f);
    p = fmaf(p, f, 6.93147180e-1f);
    p = fmaf(p, f, 1.0f);
    return __int_as_float(((int)n + 127) << 23) * p;
}
__device__ __forceinline__ unsigned pack_bf16(float a, float b) {
    __nv_bfloat162 h = __floats2bfloat162_rn(a, b);
    return *reinterpret_cast<unsigned*>(&h);
}

// ------------------- fused prep kernel --------------------------------------
#define PREP_BLOCKS (8 + 8192 + 768 + 256)

__device__ __forceinline__ void transpose_body(const float* __restrict__ W,
                                               __nv_bfloat16* __restrict__ Wt,
                                               int K, int N, int bxi, int byi) {
    __shared__ float tile[32][33];
    const int bx = bxi * 32, by = byi * 32;
    const int tx = threadIdx.x & 31, ty = threadIdx.x >> 5;
    #pragma unroll
    for (int i = 0; i < 32; i += 8)
        tile[ty + i][tx] = W[(size_t)(by + ty + i) * N + bx + tx];
    __syncthreads();
    #pragma unroll
    for (int i = 0; i < 32; i += 8)
        Wt[(size_t)(bx + ty + i) * K + by + tx] = __float2bfloat16(tile[tx][ty + i]);
}

__global__ void prep_k(const float* __restrict__ x, const void* labv,
                       const float* __restrict__ Wqkv,
                       const float* __restrict__ Wout) {
    const int b = blockIdx.x;
    if (b < 8) {
        const int lane = threadIdx.x & 31, wid = threadIdx.x >> 5;
        const long long cc = (long long)(b * 8 + wid);
        const int* a32 = (const int*)labv;
        const long long* a64 = (const long long*)labv;
        int any = 0;
        for (int i = 2 * lane + 1; i < CLA_L; i += 64) any |= a32[i];
        const bool is64 = (__ballot_sync(0xffffffffu, any != 0) == 0);
        int lt = 0;
        for (int i = lane; i < CLA_L; i += 32) {
            long long v = is64 ? a64[i] : (long long)a32[i];
            lt += (v < cc) ? 1 : 0;
        }
        #pragma unroll
        for (int o = 16; o; o >>= 1) lt += __shfl_xor_sync(0xffffffffu, lt, o);
        int pos = lt;
        for (int base = 0; base < CLA_L; base += 32) {
            long long v = is64 ? a64[base + lane] : (long long)a32[base + lane];
            unsigned m = __ballot_sync(0xffffffffu, v == cc);
            if (v == cc)
                g_order[pos + __popc(m & ((1u << lane) - 1))] = base + lane;
            pos += __popc(m);
        }
    } else if (b < 8 + 8192) {
        size_t i = ((size_t)(b - 8) * 256 + threadIdx.x) * 4;
        float4 v = *reinterpret_cast<const float4*>(x + i);
        *reinterpret_cast<__nv_bfloat162*>(g_xb + i) = __floats2bfloat162_rn(v.x, v.y);
        *reinterpret_cast<__nv_bfloat162*>(g_xb + i + 2) = __floats2bfloat162_rn(v.z, v.w);
    } else if (b < 8 + 8192 + 768) {
        const int bb = b - (8 + 8192);
        transpose_body(Wqkv, g_wqkvt, CLA_HID, CLA_QKVN, bb % 48, bb / 48);
    } else {
        const int bb = b - (8 + 8192 + 768);
        transpose_body(Wout, g_woutt, CLA_HID, CLA_HID, bb % 16, bb / 16);
    }
}

// --------- bf16 mma GEMM: block 128x128, warp 64x32, BK=32, 3-stage --------
// MODE 0: g_qkvb[m][1536] = bf16( x[g_order[m]] @ Wqkv + b )
// MODE 1: out  [m][512]   = g_attnb @ Wout + b + x[g_order[m]]   (fp32)
template <int MODE>
__global__ void __launch_bounds__(256, 2)
gemm_bf16_k(const __nv_bfloat16* __restrict__ Bt, const float* __restrict__ bias,
            const float* __restrict__ residX, float* __restrict__ outF, int N) {
    __shared__ __align__(16) unsigned char smbuf[3][16384];  // [stage][A 8K | B 8K]
    const int tid = threadIdx.x, lane = tid & 31, wid = tid >> 5;
    const int gid = lane >> 2, tig = lane & 3;
    const int wm = wid >> 2, wn = wid & 3;
    const int bm = blockIdx.y << 7, bn = blockIdx.x << 7;
    const uint32_t smbase = s2u(smbuf);

    const int r0f = tid >> 2, cf = tid & 3;
    const __nv_bfloat16* arow0;
    const __nv_bfloat16* arow1;
    if (MODE == 0) {
        arow0 = g_xb + (size_t)g_order[bm + r0f] * CLA_HID;
        arow1 = g_xb + (size_t)g_order[bm + r0f + 64] * CLA_HID;
    } else {
        arow0 = g_attnb + (size_t)(bm + r0f) * CLA_HID;
        arow1 = g_attnb + (size_t)(bm + r0f + 64) * CLA_HID;
    }
    const __nv_bfloat16* brow0 = Bt + (size_t)(bn + r0f) * CLA_HID;
    const __nv_bfloat16* brow1 = Bt + (size_t)(bn + r0f + 64) * CLA_HID;
    const uint32_t dA = r0f * 64 + ((cf ^ ((r0f >> 1) & 3)) << 4);

    float acc[4][4][4];
    #pragma unroll
    for (int i = 0; i < 4; i++)
        #pragma unroll
        for (int j = 0; j < 4; j++)
            #pragma unroll
            for (int r = 0; r < 4; r++) acc[i][j][r] = 0.f;

    const int aro = ((lane >> 3) & 1) * 8 + (lane & 7);
    const int ach = lane >> 4;
    const int bro = lane & 7;
    const int bch = (lane >> 3) & 1;
    const int sA = (aro >> 1) & 3, sB = (bro >> 1) & 3;
    uint32_t arb[4], brb[4];
    #pragma unroll
    for (int mt = 0; mt < 4; mt++) arb[mt] = (wm * 64 + mt * 16 + aro) * 64;
    #pragma unroll
    for (int nt = 0; nt < 4; nt++) brb[nt] = (wn * 32 + nt * 8 + bro) * 64 + 8192;

    #define FILL(t, b)                                                          \
        do {                                                                    \
            int kb = (t) * 64;                                                  \
            uint32_t ab = smbase + (b) * 16384;                                 \
            cp_async16(ab + dA, (const char*)arow0 + kb + cf * 16);             \
            cp_async16(ab + dA + 4096, (const char*)arow1 + kb + cf * 16);      \
            cp_async16(ab + 8192 + dA, (const char*)brow0 + kb + cf * 16);      \
            cp_async16(ab + 8192 + dA + 4096, (const char*)brow1 + kb + cf * 16);\
            cp_commit();                                                        \
        } while (0)

    FILL(0, 0);
    FILL(1, 1);
    FILL(2, 2);
    int stg = 0;
    for (int t = 0; t < 16; t++) {
        if (t < 14) cp_wait<2>();
        else if (t == 14) cp_wait<1>();
        else cp_wait<0>();
        __syncthreads();
        uint32_t base = smbase + stg * 16384;
        #pragma unroll
        for (int kk = 0; kk < 2; kk++) {
            unsigned a[4][4], b[4][2];
            #pragma unroll
            for (int mt = 0; mt < 4; mt++)
                ldsm_x4(a[mt], base + arb[mt] + (((kk * 2 + ach) ^ sA) << 4));
            #pragma unroll
            for (int nt = 0; nt < 4; nt++)
                ldsm_x2(b[nt][0], b[nt][1],
                        base + brb[nt] + (((kk * 2 + bch) ^ sB) << 4));
            #pragma unroll
            for (int mt = 0; mt < 4; mt++)
                #pragma unroll
                for (int nt = 0; nt < 4; nt++)
                    mma_bf16(acc[mt][nt], a[mt], b[nt][0], b[nt][1]);
        }
        __syncthreads();
        if (t + 3 < 16) FILL(t + 3, stg);
        stg = (stg == 2) ? 0 : stg + 1;
    }
    #undef FILL

    #pragma unroll
    for (int mt = 0; mt < 4; mt++)
        #pragma unroll
        for (int hf = 0; hf < 2; hf++) {
            int row = bm + wm * 64 + mt * 16 + hf * 8 + gid;
            int xrow = (MODE == 1) ? g_order[row] : 0;
            #pragma unroll
            for (int nt = 0; nt < 4; nt++) {
                int col = bn + wn * 32 + nt * 8 + tig * 2;
                float v0 = acc[mt][nt][hf * 2] + bias[col];
                float v1 = acc[mt][nt][hf * 2 + 1] + bias[col + 1];
                if (MODE == 0) {
                    *reinterpret_cast<__nv_bfloat162*>(
                        g_qkvb + (size_t)row * CLA_QKVN + col) =
                        __floats2bfloat162_rn(v0, v1);
                } else {
                    v0 += residX[(size_t)xrow * CLA_HID + col];
                    v1 += residX[(size_t)xrow * CLA_HID + col + 1];
                    outF[(size_t)row * CLA_HID + col] = v0;
                    outF[(size_t)row * CLA_HID + col + 1] = v1;
                }
            }
        }
}

// -- attention: 2 CTAs/(head,cluster) q-split, bf16 mma, register-P, occ 2 --
// grid 1024: half = bid&1, h = (bid>>1)&7, c = bid>>4
// smem: K [256][64]bf16 (32KB) | V (32KB); each warp owns 16 q rows
#define ATTN_SMEM_BYTES (32768 + 32768)

__global__ void __launch_bounds__(256, 2) attn_k() {
    extern __shared__ __align__(128) unsigned char smraw[];
    const uint32_t Kb = s2u(smraw);
    const uint32_t Vb = Kb + 32768;

    const int tid = threadIdx.x, lane = tid & 31, wid = tid >> 5;
    const int gid = lane >> 2, tig = lane & 3;
    const int half = blockIdx.x & 1;
    const int h = (blockIdx.x >> 1) & 7;
    const int c = blockIdx.x >> 4;
    const size_t rowbase = (size_t)c << 8;
    const int qoff = h << 6, koff = CLA_HID + qoff;
    const float Cl = 0.18033688011112042f;  // log2(e)/8

    {
        const char* krow = (const char*)(g_qkvb + (rowbase + tid) * CLA_QKVN + koff);
        const char* vrow = krow + 1024;
        const int rs = tid & 7;
        #pragma unroll
        for (int c8 = 0; c8 < 8; c8++) {
            cp_async16(Kb + (uint32_t)tid * 128 + (uint32_t)((c8 ^ rs) << 4),
                       krow + c8 * 16);
            cp_async16(Vb + (uint32_t)tid * 128 + (uint32_t)((c8 ^ rs) << 4),
                       vrow + c8 * 16);
        }
        cp_commit();
    }

    // Q fragments: this warp owns rows qr0..qr0+15 (within the cluster)
    unsigned qa[4][4];
    const int qr0 = half * 128 + wid * 16;
    {
        const __nv_bfloat16* qb = g_qkvb + rowbase * CLA_QKVN + qoff;
        #pragma unroll
        for (int ks = 0; ks < 4; ks++) {
            size_t r0 = (size_t)(qr0 + gid) * CLA_QKVN;
            size_t r1 = r0 + 8 * CLA_QKVN;
            qa[ks][0] = *reinterpret_cast<const unsigned*>(qb + r0 + ks * 16 + tig * 2);
            qa[ks][1] = *reinterpret_cast<const unsigned*>(qb + r1 + ks * 16 + tig * 2);
            qa[ks][2] = *reinterpret_cast<const unsigned*>(qb + r0 + ks * 16 + 8 + tig * 2);
            qa[ks][3] = *reinterpret_cast<const unsigned*>(qb + r1 + ks * 16 + 8 + tig * 2);
        }
    }
    cp_wait<0>();
    __syncthreads();

    const int aro = ((lane >> 3) & 1) * 8 + (lane & 7);
    const int ach = lane >> 4;

    float Oa[8][4];
    float mrow[2], srow[2];
    mrow[0] = mrow[1] = -1e30f;
    srow[0] = srow[1] = 0.f;
    #pragma unroll
    for (int n = 0; n < 8; n++)
        #pragma unroll
        for (int r = 0; r < 4; r++) Oa[n][r] = 0.f;

    for (int kt = 0; kt < 8; kt++) {
        float Sa[4][4];
        #pragma unroll
        for (int nt = 0; nt < 4; nt++)
            #pragma unroll
            for (int r = 0; r < 4; r++) Sa[nt][r] = 0.f;

        #pragma unroll
        for (int ks = 0; ks < 4; ks++) {
            unsigned kb[2][4];
            #pragma unroll
            for (int g = 0; g < 2; g++) {
                const int krw = kt * 32 + g * 16 + aro;
                ldsm_x4(kb[g], Kb + (uint32_t)krw * 128 +
                                   (uint32_t)(((ks * 2 + ach) ^ (krw & 7)) << 4));
            }
            #pragma unroll
            for (int nt = 0; nt < 4; nt++) {
                const int g = nt >> 1, p = nt & 1;
                mma_bf16(Sa[nt], qa[ks], kb[g][p], kb[g][p + 2]);
            }
        }

        // online softmax; pack P directly into mma A-operand registers
        unsigned pa[2][4];
        {
            float mx0 = -1e30f, mx1 = -1e30f;
            #pragma unroll
            for (int nt = 0; nt < 4; nt++) {
                mx0 = fmaxf(mx0, fmaxf(Sa[nt][0], Sa[nt][1]));
                mx1 = fmaxf(mx1, fmaxf(Sa[nt][2], Sa[nt][3]));
            }
            mx0 = fmaxf(mx0, __shfl_xor_sync(0xffffffffu, mx0, 1));
            mx0 = fmaxf(mx0, __shfl_xor_sync(0xffffffffu, mx0, 2));
            mx1 = fmaxf(mx1, __shfl_xor_sync(0xffffffffu, mx1, 1));
            mx1 = fmaxf(mx1, __shfl_xor_sync(0xffffffffu, mx1, 2));
            float nm0 = fmaxf(mrow[0], mx0), nm1 = fmaxf(mrow[1], mx1);
            float al0 = fexp2((mrow[0] - nm0) * Cl);
            float al1 = fexp2((mrow[1] - nm1) * Cl);
            mrow[0] = nm0; mrow[1] = nm1;
            float ps0 = 0.f, ps1 = 0.f;
            #pragma unroll
            for (int nt = 0; nt < 4; nt++) {
                float p0 = fexp2((Sa[nt][0] - nm0) * Cl);
                float p1 = fexp2((Sa[nt][1] - nm0) * Cl);
                float p2 = fexp2((Sa[nt][2] - nm1) * Cl);
                float p3 = fexp2((Sa[nt][3] - nm1) * Cl);
                ps0 += p0 + p1; ps1 += p2 + p3;
                const int ks = nt >> 1, pos = (nt & 1) * 2;
                pa[ks][pos]     = pack_bf16(p0, p1);
                pa[ks][pos + 1] = pack_bf16(p2, p3);
            }
            ps0 += __shfl_xor_sync(0xffffffffu, ps0, 1);
            ps0 += __shfl_xor_sync(0xffffffffu, ps0, 2);
            ps1 += __shfl_xor_sync(0xffffffffu, ps1, 1);
            ps1 += __shfl_xor_sync(0xffffffffu, ps1, 2);
            srow[0] = srow[0] * al0 + ps0;
            srow[1] = srow[1] * al1 + ps1;
            #pragma unroll
            for (int n = 0; n < 8; n++) {
                Oa[n][0] *= al0; Oa[n][1] *= al0;
                Oa[n][2] *= al1; Oa[n][3] *= al1;
            }
        }

        // O += P V  (P from registers, V via ldmatrix.trans)
        #pragma unroll
        for (int ks = 0; ks < 2; ks++) {
            unsigned vb[4][4];
            const int seqr = kt * 32 + ks * 16 + (lane & 15);
            #pragma unroll
            for (int g = 0; g < 4; g++) {
                const int chv = g * 2 + ach;
                ldsm_x4_t(vb[g], Vb + (uint32_t)seqr * 128 +
                                     (uint32_t)((chv ^ (seqr & 7)) << 4));
            }
            #pragma unroll
            for (int nt = 0; nt < 8; nt++) {
                const int g = nt >> 1, p = nt & 1;
                mma_bf16(Oa[nt], pa[ks], vb[g][p * 2], vb[g][p * 2 + 1]);
            }
        }
    }

    {
        float inv0 = 1.f / srow[0], inv1 = 1.f / srow[1];
        size_t r0 = rowbase + qr0 + gid;
        #pragma unroll
        for (int n = 0; n < 8; n++) {
            int cl = qoff + n * 8 + tig * 2;
            *reinterpret_cast<__nv_bfloat162*>(g_attnb + r0 * CLA_HID + cl) =
                __floats2bfloat162_rn(Oa[n][0] * inv0, Oa[n][1] * inv0);
            *reinterpret_cast<__nv_bfloat162*>(g_attnb + (r0 + 8) * CLA_HID + cl) =
                __floats2bfloat162_rn(Oa[n][2] * inv1, Oa[n][3] * inv1);
        }
    }
}

extern "C" void kernel_launch(void* const* d_in, const int* in_sizes, int n_in,
                              void* d_out, int out_size) {
    const float* x = (const float*)d_in[0];
    const void* lab = d_in[1];
    const float* Wqkv = (const float*)d_in[2];
    const float* bqkv = (const float*)d_in[3];
    const float* Wout = (const float*)d_in[4];
    const float* bout = (const float*)d_in[5];
    float* out = (float*)d_out;

    cudaFuncSetAttribute(attn_k, cudaFuncAttributeMaxDynamicSharedMemorySize,
                         ATTN_SMEM_BYTES);

    __nv_bfloat16* wqkvt; cudaGetSymbolAddress((void**)&wqkvt, g_wqkvt);
    __nv_bfloat16* woutt; cudaGetSymbolAddress((void**)&woutt, g_woutt);

    prep_k<<<PREP_BLOCKS, 256>>>(x, lab, Wqkv, Wout);
    gemm_bf16_k<0><<<dim3(12, 128), 256>>>(wqkvt, bqkv, nullptr, nullptr, CLA_QKVN);
    attn_k<<<1024, 256, ATTN_SMEM_BYTES>>>();
    gemm_bf16_k<1><<<dim3(4, 128), 256>>>(woutt, bout, x, out, CLA_HID);
}

// round 14
// speedup vs baseline: 1.5446x; 1.5446x over previous
#include <cuda_runtime.h>
#include <cuda_bf16.h>
#include <cstdint>

#define CLA_L     16384
#define CLA_HID   512
#define CLA_QKVN  1536

__device__ int           g_order[CLA_L];
__device__ __nv_bfloat16 g_xb[(size_t)CLA_L * CLA_HID];
__device__ __nv_bfloat16 g_wqkvt[(size_t)CLA_QKVN * CLA_HID];
__device__ __nv_bfloat16 g_woutt[(size_t)CLA_HID * CLA_HID];
__device__ __nv_bfloat16 g_qkvb[(size_t)CLA_L * CLA_QKVN];
__device__ __nv_bfloat16 g_attnb[(size_t)CLA_L * CLA_HID];

// ------------------------- low-level helpers -------------------------------
__device__ __forceinline__ uint32_t s2u(const void* p) {
    return (uint32_t)__cvta_generic_to_shared(p);
}
__device__ __forceinline__ void cp_async16(uint32_t dst, const void* src) {
    asm volatile("cp.async.cg.shared.global [%0], [%1], 16;\n" ::"r"(dst), "l"(src));
}
__device__ __forceinline__ void cp_commit() {
    asm volatile("cp.async.commit_group;\n");
}
template <int N> __device__ __forceinline__ void cp_wait() {
    asm volatile("cp.async.wait_group %0;\n" ::"n"(N));
}
__device__ __forceinline__ void ldsm_x4(unsigned* r, uint32_t a) {
    asm volatile("ldmatrix.sync.aligned.m8n8.x4.shared.b16 {%0,%1,%2,%3}, [%4];\n"
                 : "=r"(r[0]), "=r"(r[1]), "=r"(r[2]), "=r"(r[3]) : "r"(a));
}
__device__ __forceinline__ void ldsm_x4_t(unsigned* r, uint32_t a) {
    asm volatile("ldmatrix.sync.aligned.m8n8.x4.trans.shared.b16 {%0,%1,%2,%3}, [%4];\n"
                 : "=r"(r[0]), "=r"(r[1]), "=r"(r[2]), "=r"(r[3]) : "r"(a));
}
__device__ __forceinline__ void ldsm_x2(unsigned& r0, unsigned& r1, uint32_t a) {
    asm volatile("ldmatrix.sync.aligned.m8n8.x2.shared.b16 {%0,%1}, [%2];\n"
                 : "=r"(r0), "=r"(r1) : "r"(a));
}
__device__ __forceinline__ void mma_bf16(float* c, const unsigned* a,
                                         unsigned b0, unsigned b1) {
    asm volatile(
        "mma.sync.aligned.m16n8k16.row.col.f32.bf16.bf16.f32 "
        "{%0,%1,%2,%3},{%4,%5,%6,%7},{%8,%9},{%0,%1,%2,%3};\n"
        : "+f"(c[0]), "+f"(c[1]), "+f"(c[2]), "+f"(c[3])
        : "r"(a[0]), "r"(a[1]), "r"(a[2]), "r"(a[3]), "r"(b0), "r"(b1));
}
__device__ __forceinline__ float fexp2(float y) {
    y = fmaxf(y, -126.0f);
    float n = rintf(y);
    float f = y - n;
    float p = 1.33335581e-3f;
    p = fmaf(p, f, 9.61812910e-3f);
    p = fmaf(p, f, 5.55041087e-2f);
    p = fmaf(p, f, 2.40226507e-1f);
    p = fmaf(p, f, 6.93147180e-1f);
    p = fmaf(p, f, 1.0f);
    return __int_as_float(((int)n + 127) << 23) * p;
}
__device__ __forceinline__ unsigned pack_bf16(float a, float b) {
    __nv_bfloat162 h = __floats2bfloat162_rn(a, b);
    return *reinterpret_cast<unsigned*>(&h);
}

// ------------------- fused prep kernel --------------------------------------
#define PREP_BLOCKS (8 + 8192 + 768 + 256)

__device__ __forceinline__ void transpose_body(const float* __restrict__ W,
                                               __nv_bfloat16* __restrict__ Wt,
                                               int K, int N, int bxi, int byi) {
    __shared__ float tile[32][33];
    const int bx = bxi * 32, by = byi * 32;
    const int tx = threadIdx.x & 31, ty = threadIdx.x >> 5;
    #pragma unroll
    for (int i = 0; i < 32; i += 8)
        tile[ty + i][tx] = W[(size_t)(by + ty + i) * N + bx + tx];
    __syncthreads();
    #pragma unroll
    for (int i = 0; i < 32; i += 8)
        Wt[(size_t)(bx + ty + i) * K + by + tx] = __float2bfloat16(tile[tx][ty + i]);
}

__global__ void prep_k(const float* __restrict__ x, const void* labv,
                       const float* __restrict__ Wqkv,
                       const float* __restrict__ Wout) {
    const int b = blockIdx.x;
    if (b < 8) {
        const int lane = threadIdx.x & 31, wid = threadIdx.x >> 5;
        const long long cc = (long long)(b * 8 + wid);
        const int* a32 = (const int*)labv;
        const long long* a64 = (const long long*)labv;
        int any = 0;
        for (int i = 2 * lane + 1; i < CLA_L; i += 64) any |= a32[i];
        const bool is64 = (__ballot_sync(0xffffffffu, any != 0) == 0);
        int lt = 0;
        for (int i = lane; i < CLA_L; i += 32) {
            long long v = is64 ? a64[i] : (long long)a32[i];
            lt += (v < cc) ? 1 : 0;
        }
        #pragma unroll
        for (int o = 16; o; o >>= 1) lt += __shfl_xor_sync(0xffffffffu, lt, o);
        int pos = lt;
        for (int base = 0; base < CLA_L; base += 32) {
            long long v = is64 ? a64[base + lane] : (long long)a32[base + lane];
            unsigned m = __ballot_sync(0xffffffffu, v == cc);
            if (v == cc)
                g_order[pos + __popc(m & ((1u << lane) - 1))] = base + lane;
            pos += __popc(m);
        }
    } else if (b < 8 + 8192) {
        size_t i = ((size_t)(b - 8) * 256 + threadIdx.x) * 4;
        float4 v = *reinterpret_cast<const float4*>(x + i);
        *reinterpret_cast<__nv_bfloat162*>(g_xb + i) = __floats2bfloat162_rn(v.x, v.y);
        *reinterpret_cast<__nv_bfloat162*>(g_xb + i + 2) = __floats2bfloat162_rn(v.z, v.w);
    } else if (b < 8 + 8192 + 768) {
        const int bb = b - (8 + 8192);
        transpose_body(Wqkv, g_wqkvt, CLA_HID, CLA_QKVN, bb % 48, bb / 48);
    } else {
        const int bb = b - (8 + 8192 + 768);
        transpose_body(Wout, g_woutt, CLA_HID, CLA_HID, bb % 16, bb / 16);
    }
}

// --------- bf16 mma GEMM: block 128x128, warp 64x32, BK=32, 3-stage --------
// MODE 0: g_qkvb[m][1536] = bf16( x[g_order[m]] @ Wqkv + b )
// MODE 1: out  [m][512]   = g_attnb @ Wout + b + x[g_order[m]]   (fp32)
template <int MODE>
__global__ void __launch_bounds__(256, 2)
gemm_bf16_k(const __nv_bfloat16* __restrict__ Bt, const float* __restrict__ bias,
            const float* __restrict__ residX, float* __restrict__ outF, int N) {
    __shared__ __align__(16) unsigned char smbuf[3][16384];  // [stage][A 8K | B 8K]
    const int tid = threadIdx.x, lane = tid & 31, wid = tid >> 5;
    const int gid = lane >> 2, tig = lane & 3;
    const int wm = wid >> 2, wn = wid & 3;
    const int bm = blockIdx.y << 7, bn = blockIdx.x << 7;
    const uint32_t smbase = s2u(smbuf);

    const int r0f = tid >> 2, cf = tid & 3;
    const __nv_bfloat16* arow0;
    const __nv_bfloat16* arow1;
    if (MODE == 0) {
        arow0 = g_xb + (size_t)g_order[bm + r0f] * CLA_HID;
        arow1 = g_xb + (size_t)g_order[bm + r0f + 64] * CLA_HID;
    } else {
        arow0 = g_attnb + (size_t)(bm + r0f) * CLA_HID;
        arow1 = g_attnb + (size_t)(bm + r0f + 64) * CLA_HID;
    }
    const __nv_bfloat16* brow0 = Bt + (size_t)(bn + r0f) * CLA_HID;
    const __nv_bfloat16* brow1 = Bt + (size_t)(bn + r0f + 64) * CLA_HID;
    const uint32_t dA = r0f * 64 + ((cf ^ ((r0f >> 1) & 3)) << 4);

    float acc[4][4][4];
    #pragma unroll
    for (int i = 0; i < 4; i++)
        #pragma unroll
        for (int j = 0; j < 4; j++)
            #pragma unroll
            for (int r = 0; r < 4; r++) acc[i][j][r] = 0.f;

    const int aro = ((lane >> 3) & 1) * 8 + (lane & 7);
    const int ach = lane >> 4;
    const int bro = lane & 7;
    const int bch = (lane >> 3) & 1;
    const int sA = (aro >> 1) & 3, sB = (bro >> 1) & 3;
    uint32_t arb[4], brb[4];
    #pragma unroll
    for (int mt = 0; mt < 4; mt++) arb[mt] = (wm * 64 + mt * 16 + aro) * 64;
    #pragma unroll
    for (int nt = 0; nt < 4; nt++) brb[nt] = (wn * 32 + nt * 8 + bro) * 64 + 8192;

    #define FILL(t, b)                                                          \
        do {                                                                    \
            int kb = (t) * 64;                                                  \
            uint32_t ab = smbase + (b) * 16384;                                 \
            cp_async16(ab + dA, (const char*)arow0 + kb + cf * 16);             \
            cp_async16(ab + dA + 4096, (const char*)arow1 + kb + cf * 16);      \
            cp_async16(ab + 8192 + dA, (const char*)brow0 + kb + cf * 16);      \
            cp_async16(ab + 8192 + dA + 4096, (const char*)brow1 + kb + cf * 16);\
            cp_commit();                                                        \
        } while (0)

    FILL(0, 0);
    FILL(1, 1);
    FILL(2, 2);
    int stg = 0;
    for (int t = 0; t < 16; t++) {
        if (t < 14) cp_wait<2>();
        else if (t == 14) cp_wait<1>();
        else cp_wait<0>();
        __syncthreads();
        uint32_t base = smbase + stg * 16384;
        #pragma unroll
        for (int kk = 0; kk < 2; kk++) {
            unsigned a[4][4], b[4][2];
            #pragma unroll
            for (int mt = 0; mt < 4; mt++)
                ldsm_x4(a[mt], base + arb[mt] + (((kk * 2 + ach) ^ sA) << 4));
            #pragma unroll
            for (int nt = 0; nt < 4; nt++)
                ldsm_x2(b[nt][0], b[nt][1],
                        base + brb[nt] + (((kk * 2 + bch) ^ sB) << 4));
            #pragma unroll
            for (int mt = 0; mt < 4; mt++)
                #pragma unroll
                for (int nt = 0; nt < 4; nt++)
                    mma_bf16(acc[mt][nt], a[mt], b[nt][0], b[nt][1]);
        }
        __syncthreads();
        if (t + 3 < 16) FILL(t + 3, stg);
        stg = (stg == 2) ? 0 : stg + 1;
    }
    #undef FILL

    #pragma unroll
    for (int mt = 0; mt < 4; mt++)
        #pragma unroll
        for (int hf = 0; hf < 2; hf++) {
            int row = bm + wm * 64 + mt * 16 + hf * 8 + gid;
            int xrow = (MODE == 1) ? g_order[row] : 0;
            #pragma unroll
            for (int nt = 0; nt < 4; nt++) {
                int col = bn + wn * 32 + nt * 8 + tig * 2;
                float v0 = acc[mt][nt][hf * 2] + bias[col];
                float v1 = acc[mt][nt][hf * 2 + 1] + bias[col + 1];
                if (MODE == 0) {
                    *reinterpret_cast<__nv_bfloat162*>(
                        g_qkvb + (size_t)row * CLA_QKVN + col) =
                        __floats2bfloat162_rn(v0, v1);
                } else {
                    float2 rr = *reinterpret_cast<const float2*>(
                        residX + (size_t)xrow * CLA_HID + col);
                    float2 ov = make_float2(v0 + rr.x, v1 + rr.y);
                    *reinterpret_cast<float2*>(outF + (size_t)row * CLA_HID + col) = ov;
                }
            }
        }
}

// ---- attention: 1 CTA/(head,cluster), bf16 mma, register-P, full regs -----
#define ATTN_SMEM_BYTES (32768 + 32768)

__global__ void __launch_bounds__(256, 1) attn_k() {
    extern __shared__ __align__(128) unsigned char smraw[];
    const uint32_t Kb = s2u(smraw);
    const uint32_t Vb = Kb + 32768;

    const int tid = threadIdx.x, lane = tid & 31, wid = tid >> 5;
    const int gid = lane >> 2, tig = lane & 3;
    const int h = blockIdx.x & 7, c = blockIdx.x >> 3;
    const size_t rowbase = (size_t)c << 8;
    const int qoff = h << 6, koff = CLA_HID + qoff;
    const float Cl = 0.18033688011112042f;  // log2(e)/8

    {
        const char* krow = (const char*)(g_qkvb + (rowbase + tid) * CLA_QKVN + koff);
        const char* vrow = krow + 1024;
        const int rs = tid & 7;
        #pragma unroll
        for (int c8 = 0; c8 < 8; c8++) {
            cp_async16(Kb + (uint32_t)tid * 128 + (uint32_t)((c8 ^ rs) << 4),
                       krow + c8 * 16);
            cp_async16(Vb + (uint32_t)tid * 128 + (uint32_t)((c8 ^ rs) << 4),
                       vrow + c8 * 16);
        }
        cp_commit();
    }

    unsigned qa[2][4][4];
    {
        const __nv_bfloat16* qb = g_qkvb + rowbase * CLA_QKVN + qoff;
        const int qr0 = wid * 32;
        #pragma unroll
        for (int mt = 0; mt < 2; mt++)
            #pragma unroll
            for (int ks = 0; ks < 4; ks++) {
                size_t r0 = (size_t)(qr0 + mt * 16 + gid) * CLA_QKVN;
                size_t r1 = r0 + 8 * CLA_QKVN;
                qa[mt][ks][0] = *reinterpret_cast<const unsigned*>(qb + r0 + ks * 16 + tig * 2);
                qa[mt][ks][1] = *reinterpret_cast<const unsigned*>(qb + r1 + ks * 16 + tig * 2);
                qa[mt][ks][2] = *reinterpret_cast<const unsigned*>(qb + r0 + ks * 16 + 8 + tig * 2);
                qa[mt][ks][3] = *reinterpret_cast<const unsigned*>(qb + r1 + ks * 16 + 8 + tig * 2);
            }
    }
    cp_wait<0>();
    __syncthreads();

    const int aro = ((lane >> 3) & 1) * 8 + (lane & 7);
    const int ach = lane >> 4;

    float Oa[2][8][4];
    float mrow[2][2], srow[2][2];
    #pragma unroll
    for (int mt = 0; mt < 2; mt++) {
        mrow[mt][0] = mrow[mt][1] = -1e30f;
        srow[mt][0] = srow[mt][1] = 0.f;
        #pragma unroll
        for (int n = 0; n < 8; n++)
            #pragma unroll
            for (int r = 0; r < 4; r++) Oa[mt][n][r] = 0.f;
    }

    for (int kt = 0; kt < 8; kt++) {
        float Sa[2][4][4];
        #pragma unroll
        for (int mt = 0; mt < 2; mt++)
            #pragma unroll
            for (int nt = 0; nt < 4; nt++)
                #pragma unroll
                for (int r = 0; r < 4; r++) Sa[mt][nt][r] = 0.f;

        #pragma unroll
        for (int ks = 0; ks < 4; ks++) {
            unsigned kb[2][4];
            #pragma unroll
            for (int g = 0; g < 2; g++) {
                const int krw = kt * 32 + g * 16 + aro;
                ldsm_x4(kb[g], Kb + (uint32_t)krw * 128 +
                                   (uint32_t)(((ks * 2 + ach) ^ (krw & 7)) << 4));
            }
            #pragma unroll
            for (int mt = 0; mt < 2; mt++)
                #pragma unroll
                for (int nt = 0; nt < 4; nt++) {
                    const int g = nt >> 1, p = nt & 1;
                    mma_bf16(Sa[mt][nt], qa[mt][ks], kb[g][p], kb[g][p + 2]);
                }
        }

        // online softmax; pack P directly into mma A-operand registers
        unsigned pa[2][2][4];
        #pragma unroll
        for (int mt = 0; mt < 2; mt++) {
            float mx0 = -1e30f, mx1 = -1e30f;
            #pragma unroll
            for (int nt = 0; nt < 4; nt++) {
                mx0 = fmaxf(mx0, fmaxf(Sa[mt][nt][0], Sa[mt][nt][1]));
                mx1 = fmaxf(mx1, fmaxf(Sa[mt][nt][2], Sa[mt][nt][3]));
            }
            mx0 = fmaxf(mx0, __shfl_xor_sync(0xffffffffu, mx0, 1));
            mx0 = fmaxf(mx0, __shfl_xor_sync(0xffffffffu, mx0, 2));
            mx1 = fmaxf(mx1, __shfl_xor_sync(0xffffffffu, mx1, 1));
            mx1 = fmaxf(mx1, __shfl_xor_sync(0xffffffffu, mx1, 2));
            float nm0 = fmaxf(mrow[mt][0], mx0), nm1 = fmaxf(mrow[mt][1], mx1);
            float al0 = fexp2((mrow[mt][0] - nm0) * Cl);
            float al1 = fexp2((mrow[mt][1] - nm1) * Cl);
            mrow[mt][0] = nm0; mrow[mt][1] = nm1;
            float ps0 = 0.f, ps1 = 0.f;
            #pragma unroll
            for (int nt = 0; nt < 4; nt++) {
                float p0 = fexp2((Sa[mt][nt][0] - nm0) * Cl);
                float p1 = fexp2((Sa[mt][nt][1] - nm0) * Cl);
                float p2 = fexp2((Sa[mt][nt][2] - nm1) * Cl);
                float p3 = fexp2((Sa[mt][nt][3] - nm1) * Cl);
                ps0 += p0 + p1; ps1 += p2 + p3;
                const int ks = nt >> 1, pos = (nt & 1) * 2;
                pa[mt][ks][pos]     = pack_bf16(p0, p1);
                pa[mt][ks][pos + 1] = pack_bf16(p2, p3);
            }
            ps0 += __shfl_xor_sync(0xffffffffu, ps0, 1);
            ps0 += __shfl_xor_sync(0xffffffffu, ps0, 2);
            ps1 += __shfl_xor_sync(0xffffffffu, ps1, 1);
            ps1 += __shfl_xor_sync(0xffffffffu, ps1, 2);
            srow[mt][0] = srow[mt][0] * al0 + ps0;
            srow[mt][1] = srow[mt][1] * al1 + ps1;
            #pragma unroll
            for (int n = 0; n < 8; n++) {
                Oa[mt][n][0] *= al0; Oa[mt][n][1] *= al0;
                Oa[mt][n][2] *= al1; Oa[mt][n][3] *= al1;
            }
        }

        // O += P V  (P from registers, V via ldmatrix.trans)
        #pragma unroll
        for (int ks = 0; ks < 2; ks++) {
            unsigned vb[4][4];
            const int seqr = kt * 32 + ks * 16 + (lane & 15);
            #pragma unroll
            for (int g = 0; g < 4; g++) {
                const int chv = g * 2 + ach;
                ldsm_x4_t(vb[g], Vb + (uint32_t)seqr * 128 +
                                     (uint32_t)((chv ^ (seqr & 7)) << 4));
            }
            #pragma unroll
            for (int mt = 0; mt < 2; mt++)
                #pragma unroll
                for (int nt = 0; nt < 8; nt++) {
                    const int g = nt >> 1, p = nt & 1;
                    mma_bf16(Oa[mt][nt], pa[mt][ks], vb[g][p * 2], vb[g][p * 2 + 1]);
                }
        }
    }

    #pragma unroll
    for (int mt = 0; mt < 2; mt++) {
        float inv0 = 1.f / srow[mt][0], inv1 = 1.f / srow[mt][1];
        size_t r0 = rowbase + wid * 32 + mt * 16 + gid;
        #pragma unroll
        for (int n = 0; n < 8; n++) {
            int cl = qoff + n * 8 + tig * 2;
            *reinterpret_cast<__nv_bfloat162*>(g_attnb + r0 * CLA_HID + cl) =
                __floats2bfloat162_rn(Oa[mt][n][0] * inv0, Oa[mt][n][1] * inv0);
            *reinterpret_cast<__nv_bfloat162*>(g_attnb + (r0 + 8) * CLA_HID + cl) =
                __floats2bfloat162_rn(Oa[mt][n][2] * inv1, Oa[mt][n][3] * inv1);
        }
    }
}

extern "C" void kernel_launch(void* const* d_in, const int* in_sizes, int n_in,
                              void* d_out, int out_size) {
    const float* x = (const float*)d_in[0];
    const void* lab = d_in[1];
    const float* Wqkv = (const float*)d_in[2];
    const float* bqkv = (const float*)d_in[3];
    const float* Wout = (const float*)d_in[4];
    const float* bout = (const float*)d_in[5];
    float* out = (float*)d_out;

    cudaFuncSetAttribute(attn_k, cudaFuncAttributeMaxDynamicSharedMemorySize,
                         ATTN_SMEM_BYTES);

    __nv_bfloat16* wqkvt; cudaGetSymbolAddress((void**)&wqkvt, g_wqkvt);
    __nv_bfloat16* woutt; cudaGetSymbolAddress((void**)&woutt, g_woutt);

    prep_k<<<PREP_BLOCKS, 256>>>(x, lab, Wqkv, Wout);
    gemm_bf16_k<0><<<dim3(12, 128), 256>>>(wqkvt, bqkv, nullptr, nullptr, CLA_QKVN);
    attn_k<<<512, 256, ATTN_SMEM_BYTES>>>();
    gemm_bf16_k<1><<<dim3(4, 128), 256>>>(woutt, bout, x, out, CLA_HID);
}

// round 15
// speedup vs baseline: 1.5581x; 1.0087x over previous
#include <cuda_runtime.h>
#include <cuda_bf16.h>
#include <cstdint>

#define CLA_L     16384
#define CLA_HID   512
#define CLA_QKVN  1536

__device__ int           g_order[CLA_L];
__device__ __nv_bfloat16 g_xb[(size_t)CLA_L * CLA_HID];
__device__ __nv_bfloat16 g_wqkvt[(size_t)CLA_QKVN * CLA_HID];
__device__ __nv_bfloat16 g_woutt[(size_t)CLA_HID * CLA_HID];
__device__ __nv_bfloat16 g_qkvb[(size_t)CLA_L * CLA_QKVN];
__device__ __nv_bfloat16 g_attnb[(size_t)CLA_L * CLA_HID];

// ------------------------- low-level helpers -------------------------------
__device__ __forceinline__ uint32_t s2u(const void* p) {
    return (uint32_t)__cvta_generic_to_shared(p);
}
__device__ __forceinline__ void cp_async16(uint32_t dst, const void* src) {
    asm volatile("cp.async.cg.shared.global [%0], [%1], 16;\n" ::"r"(dst), "l"(src));
}
__device__ __forceinline__ void cp_commit() {
    asm volatile("cp.async.commit_group;\n");
}
template <int N> __device__ __forceinline__ void cp_wait() {
    asm volatile("cp.async.wait_group %0;\n" ::"n"(N));
}
__device__ __forceinline__ void ldsm_x4(unsigned* r, uint32_t a) {
    asm volatile("ldmatrix.sync.aligned.m8n8.x4.shared.b16 {%0,%1,%2,%3}, [%4];\n"
                 : "=r"(r[0]), "=r"(r[1]), "=r"(r[2]), "=r"(r[3]) : "r"(a));
}
__device__ __forceinline__ void ldsm_x4_t(unsigned* r, uint32_t a) {
    asm volatile("ldmatrix.sync.aligned.m8n8.x4.trans.shared.b16 {%0,%1,%2,%3}, [%4];\n"
                 : "=r"(r[0]), "=r"(r[1]), "=r"(r[2]), "=r"(r[3]) : "r"(a));
}
__device__ __forceinline__ void ldsm_x2(unsigned& r0, unsigned& r1, uint32_t a) {
    asm volatile("ldmatrix.sync.aligned.m8n8.x2.shared.b16 {%0,%1}, [%2];\n"
                 : "=r"(r0), "=r"(r1) : "r"(a));
}
__device__ __forceinline__ void mma_bf16(float* c, const unsigned* a,
                                         unsigned b0, unsigned b1) {
    asm volatile(
        "mma.sync.aligned.m16n8k16.row.col.f32.bf16.bf16.f32 "
        "{%0,%1,%2,%3},{%4,%5,%6,%7},{%8,%9},{%0,%1,%2,%3};\n"
        : "+f"(c[0]), "+f"(c[1]), "+f"(c[2]), "+f"(c[3])
        : "r"(a[0]), "r"(a[1]), "r"(a[2]), "r"(a[3]), "r"(b0), "r"(b1));
}
__device__ __forceinline__ float fexp2(float y) {
    y = fmaxf(y, -126.0f);
    float n = rintf(y);
    float f = y - n;
    float p = 1.33335581e-3f;
    p = fmaf(p, f, 9.61812910e-3f);
    p = fmaf(p, f, 5.55041087e-2f);
    p = fmaf(p, f, 2.40226507e-1f);
    p = fmaf(p, f, 6.93147180e-1f);
    p = fmaf(p, f, 1.0f);
    return __int_as_float(((int)n + 127) << 23) * p;
}
__device__ __forceinline__ unsigned pack_bf16(float a, float b) {
    __nv_bfloat162 h = __floats2bfloat162_rn(a, b);
    return *reinterpret_cast<unsigned*>(&h);
}

// ------------------- fused prep kernel --------------------------------------
#define PREP_BLOCKS (8 + 8192 + 768 + 256)

__device__ __forceinline__ void transpose_body(const float* __restrict__ W,
                                               __nv_bfloat16* __restrict__ Wt,
                                               int K, int N, int bxi, int byi) {
    __shared__ float tile[32][33];
    const int bx = bxi * 32, by = byi * 32;
    const int tx = threadIdx.x & 31, ty = threadIdx.x >> 5;
    #pragma unroll
    for (int i = 0; i < 32; i += 8)
        tile[ty + i][tx] = W[(size_t)(by + ty + i) * N + bx + tx];
    __syncthreads();
    #pragma unroll
    for (int i = 0; i < 32; i += 8)
        Wt[(size_t)(bx + ty + i) * K + by + tx] = __float2bfloat16(tile[tx][ty + i]);
}

__global__ void prep_k(const float* __restrict__ x, const void* labv,
                       const float* __restrict__ Wqkv,
                       const float* __restrict__ Wout) {
    const int b = blockIdx.x;
    if (b < 8) {
        const int lane = threadIdx.x & 31, wid = threadIdx.x >> 5;
        const long long cc = (long long)(b * 8 + wid);
        const int* a32 = (const int*)labv;
        const long long* a64 = (const long long*)labv;
        int any = 0;
        for (int i = 2 * lane + 1; i < CLA_L; i += 64) any |= a32[i];
        const bool is64 = (__ballot_sync(0xffffffffu, any != 0) == 0);
        int lt = 0;
        for (int i = lane; i < CLA_L; i += 32) {
            long long v = is64 ? a64[i] : (long long)a32[i];
            lt += (v < cc) ? 1 : 0;
        }
        #pragma unroll
        for (int o = 16; o; o >>= 1) lt += __shfl_xor_sync(0xffffffffu, lt, o);
        int pos = lt;
        for (int base = 0; base < CLA_L; base += 32) {
            long long v = is64 ? a64[base + lane] : (long long)a32[base + lane];
            unsigned m = __ballot_sync(0xffffffffu, v == cc);
            if (v == cc)
                g_order[pos + __popc(m & ((1u << lane) - 1))] = base + lane;
            pos += __popc(m);
        }
    } else if (b < 8 + 8192) {
        size_t i = ((size_t)(b - 8) * 256 + threadIdx.x) * 4;
        float4 v = *reinterpret_cast<const float4*>(x + i);
        *reinterpret_cast<__nv_bfloat162*>(g_xb + i) = __floats2bfloat162_rn(v.x, v.y);
        *reinterpret_cast<__nv_bfloat162*>(g_xb + i + 2) = __floats2bfloat162_rn(v.z, v.w);
    } else if (b < 8 + 8192 + 768) {
        const int bb = b - (8 + 8192);
        transpose_body(Wqkv, g_wqkvt, CLA_HID, CLA_QKVN, bb % 48, bb / 48);
    } else {
        const int bb = b - (8 + 8192 + 768);
        transpose_body(Wout, g_woutt, CLA_HID, CLA_HID, bb % 16, bb / 16);
    }
}

// --------- bf16 mma GEMM: block 128x128, warp 64x32, BK=32, 3-stage --------
// MODE 0: g_qkvb[m][1536] = bf16( x[g_order[m]] @ Wqkv + b )
// MODE 1: out  [m][512]   = g_attnb @ Wout + b + x[g_order[m]]   (fp32)
template <int MODE>
__global__ void __launch_bounds__(256, 2)
gemm_bf16_k(const __nv_bfloat16* __restrict__ Bt, const float* __restrict__ bias,
            const float* __restrict__ residX, float* __restrict__ outF, int N) {
    __shared__ __align__(16) unsigned char smbuf[3][16384];  // [stage][A 8K | B 8K]
    const int tid = threadIdx.x, lane = tid & 31, wid = tid >> 5;
    const int gid = lane >> 2, tig = lane & 3;
    const int wm = wid >> 2, wn = wid & 3;
    const int bm = blockIdx.y << 7, bn = blockIdx.x << 7;
    const uint32_t smbase = s2u(smbuf);

    const int r0f = tid >> 2, cf = tid & 3;
    const __nv_bfloat16* arow0;
    const __nv_bfloat16* arow1;
    if (MODE == 0) {
        arow0 = g_xb + (size_t)g_order[bm + r0f] * CLA_HID;
        arow1 = g_xb + (size_t)g_order[bm + r0f + 64] * CLA_HID;
    } else {
        arow0 = g_attnb + (size_t)(bm + r0f) * CLA_HID;
        arow1 = g_attnb + (size_t)(bm + r0f + 64) * CLA_HID;
    }
    const __nv_bfloat16* brow0 = Bt + (size_t)(bn + r0f) * CLA_HID;
    const __nv_bfloat16* brow1 = Bt + (size_t)(bn + r0f + 64) * CLA_HID;
    const uint32_t dA = r0f * 64 + ((cf ^ ((r0f >> 1) & 3)) << 4);

    float acc[4][4][4];
    #pragma unroll
    for (int i = 0; i < 4; i++)
        #pragma unroll
        for (int j = 0; j < 4; j++)
            #pragma unroll
            for (int r = 0; r < 4; r++) acc[i][j][r] = 0.f;

    const int aro = ((lane >> 3) & 1) * 8 + (lane & 7);
    const int ach = lane >> 4;
    const int bro = lane & 7;
    const int bch = (lane >> 3) & 1;
    const int sA = (aro >> 1) & 3, sB = (bro >> 1) & 3;
    uint32_t arb[4], brb[4];
    #pragma unroll
    for (int mt = 0; mt < 4; mt++) arb[mt] = (wm * 64 + mt * 16 + aro) * 64;
    #pragma unroll
    for (int nt = 0; nt < 4; nt++) brb[nt] = (wn * 32 + nt * 8 + bro) * 64 + 8192;

    #define FILL(t, b)                                                          \
        do {                                                                    \
            int kb = (t) * 64;                                                  \
            uint32_t ab = smbase + (b) * 16384;                                 \
            cp_async16(ab + dA, (const char*)arow0 + kb + cf * 16);             \
            cp_async16(ab + dA + 4096, (const char*)arow1 + kb + cf * 16);      \
            cp_async16(ab + 8192 + dA, (const char*)brow0 + kb + cf * 16);      \
            cp_async16(ab + 8192 + dA + 4096, (const char*)brow1 + kb + cf * 16);\
            cp_commit();                                                        \
        } while (0)

    FILL(0, 0);
    FILL(1, 1);
    FILL(2, 2);
    int stg = 0;
    for (int t = 0; t < 16; t++) {
        if (t < 14) cp_wait<2>();
        else if (t == 14) cp_wait<1>();
        else cp_wait<0>();
        __syncthreads();
        uint32_t base = smbase + stg * 16384;
        #pragma unroll
        for (int kk = 0; kk < 2; kk++) {
            unsigned a[4][4], b[4][2];
            #pragma unroll
            for (int mt = 0; mt < 4; mt++)
                ldsm_x4(a[mt], base + arb[mt] + (((kk * 2 + ach) ^ sA) << 4));
            #pragma unroll
            for (int nt = 0; nt < 4; nt++)
                ldsm_x2(b[nt][0], b[nt][1],
                        base + brb[nt] + (((kk * 2 + bch) ^ sB) << 4));
            #pragma unroll
            for (int mt = 0; mt < 4; mt++)
                #pragma unroll
                for (int nt = 0; nt < 4; nt++)
                    mma_bf16(acc[mt][nt], a[mt], b[nt][0], b[nt][1]);
        }
        __syncthreads();
        if (t + 3 < 16) FILL(t + 3, stg);
        stg = (stg == 2) ? 0 : stg + 1;
    }
    #undef FILL

    #pragma unroll
    for (int mt = 0; mt < 4; mt++)
        #pragma unroll
        for (int hf = 0; hf < 2; hf++) {
            int row = bm + wm * 64 + mt * 16 + hf * 8 + gid;
            int xrow = (MODE == 1) ? g_order[row] : 0;
            #pragma unroll
            for (int nt = 0; nt < 4; nt++) {
                int col = bn + wn * 32 + nt * 8 + tig * 2;
                float v0 = acc[mt][nt][hf * 2] + bias[col];
                float v1 = acc[mt][nt][hf * 2 + 1] + bias[col + 1];
                if (MODE == 0) {
                    *reinterpret_cast<__nv_bfloat162*>(
                        g_qkvb + (size_t)row * CLA_QKVN + col) =
                        __floats2bfloat162_rn(v0, v1);
                } else {
                    float2 rr = *reinterpret_cast<const float2*>(
                        residX + (size_t)xrow * CLA_HID + col);
                    float2 ov = make_float2(v0 + rr.x, v1 + rr.y);
                    *reinterpret_cast<float2*>(outF + (size_t)row * CLA_HID + col) = ov;
                }
            }
        }
}

// -- attention: 1 CTA (512 thr, 16 warps) per (head,cluster); 16 q-rows/warp -
// smem: K [256][64]bf16 (32KB) | V (32KB); register-P
#define ATTN_SMEM_BYTES (32768 + 32768)

__global__ void __launch_bounds__(512, 1) attn_k() {
    extern __shared__ __align__(128) unsigned char smraw[];
    const uint32_t Kb = s2u(smraw);
    const uint32_t Vb = Kb + 32768;

    const int tid = threadIdx.x, lane = tid & 31, wid = tid >> 5;
    const int gid = lane >> 2, tig = lane & 3;
    const int h = blockIdx.x & 7, c = blockIdx.x >> 3;
    const size_t rowbase = (size_t)c << 8;
    const int qoff = h << 6, koff = CLA_HID + qoff;
    const float Cl = 0.18033688011112042f;  // log2(e)/8

    // K,V -> smem: 512 threads, each loads 4 chunks of one half-row
    {
        const int r = tid >> 1;                 // 0..255
        const int cb = (tid & 1) * 4;           // chunk base 0 or 4
        const int rs = r & 7;
        const char* krow = (const char*)(g_qkvb + (rowbase + r) * CLA_QKVN + koff);
        const char* vrow = krow + 1024;
        #pragma unroll
        for (int i = 0; i < 4; i++) {
            const int c8 = cb + i;
            cp_async16(Kb + (uint32_t)r * 128 + (uint32_t)((c8 ^ rs) << 4),
                       krow + c8 * 16);
            cp_async16(Vb + (uint32_t)r * 128 + (uint32_t)((c8 ^ rs) << 4),
                       vrow + c8 * 16);
        }
        cp_commit();
    }

    // Q fragments: this warp owns q rows qr0..qr0+15
    unsigned qa[4][4];
    const int qr0 = wid * 16;
    {
        const __nv_bfloat16* qb = g_qkvb + rowbase * CLA_QKVN + qoff;
        #pragma unroll
        for (int ks = 0; ks < 4; ks++) {
            size_t r0 = (size_t)(qr0 + gid) * CLA_QKVN;
            size_t r1 = r0 + 8 * CLA_QKVN;
            qa[ks][0] = *reinterpret_cast<const unsigned*>(qb + r0 + ks * 16 + tig * 2);
            qa[ks][1] = *reinterpret_cast<const unsigned*>(qb + r1 + ks * 16 + tig * 2);
            qa[ks][2] = *reinterpret_cast<const unsigned*>(qb + r0 + ks * 16 + 8 + tig * 2);
            qa[ks][3] = *reinterpret_cast<const unsigned*>(qb + r1 + ks * 16 + 8 + tig * 2);
        }
    }
    cp_wait<0>();
    __syncthreads();

    const int aro = ((lane >> 3) & 1) * 8 + (lane & 7);
    const int ach = lane >> 4;

    float Oa[8][4];
    float mrow[2], srow[2];
    mrow[0] = mrow[1] = -1e30f;
    srow[0] = srow[1] = 0.f;
    #pragma unroll
    for (int n = 0; n < 8; n++)
        #pragma unroll
        for (int r = 0; r < 4; r++) Oa[n][r] = 0.f;

    for (int kt = 0; kt < 8; kt++) {
        float Sa[4][4];
        #pragma unroll
        for (int nt = 0; nt < 4; nt++)
            #pragma unroll
            for (int r = 0; r < 4; r++) Sa[nt][r] = 0.f;

        #pragma unroll
        for (int ks = 0; ks < 4; ks++) {
            unsigned kb[2][4];
            #pragma unroll
            for (int g = 0; g < 2; g++) {
                const int krw = kt * 32 + g * 16 + aro;
                ldsm_x4(kb[g], Kb + (uint32_t)krw * 128 +
                                   (uint32_t)(((ks * 2 + ach) ^ (krw & 7)) << 4));
            }
            #pragma unroll
            for (int nt = 0; nt < 4; nt++) {
                const int g = nt >> 1, p = nt & 1;
                mma_bf16(Sa[nt], qa[ks], kb[g][p], kb[g][p + 2]);
            }
        }

        // online softmax; pack P directly into mma A-operand registers
        unsigned pa[2][4];
        {
            float mx0 = -1e30f, mx1 = -1e30f;
            #pragma unroll
            for (int nt = 0; nt < 4; nt++) {
                mx0 = fmaxf(mx0, fmaxf(Sa[nt][0], Sa[nt][1]));
                mx1 = fmaxf(mx1, fmaxf(Sa[nt][2], Sa[nt][3]));
            }
            mx0 = fmaxf(mx0, __shfl_xor_sync(0xffffffffu, mx0, 1));
            mx0 = fmaxf(mx0, __shfl_xor_sync(0xffffffffu, mx0, 2));
            mx1 = fmaxf(mx1, __shfl_xor_sync(0xffffffffu, mx1, 1));
            mx1 = fmaxf(mx1, __shfl_xor_sync(0xffffffffu, mx1, 2));
            float nm0 = fmaxf(mrow[0], mx0), nm1 = fmaxf(mrow[1], mx1);
            float al0 = fexp2((mrow[0] - nm0) * Cl);
            float al1 = fexp2((mrow[1] - nm1) * Cl);
            mrow[0] = nm0; mrow[1] = nm1;
            float ps0 = 0.f, ps1 = 0.f;
            #pragma unroll
            for (int nt = 0; nt < 4; nt++) {
                float p0 = fexp2((Sa[nt][0] - nm0) * Cl);
                float p1 = fexp2((Sa[nt][1] - nm0) * Cl);
                float p2 = fexp2((Sa[nt][2] - nm1) * Cl);
                float p3 = fexp2((Sa[nt][3] - nm1) * Cl);
                ps0 += p0 + p1; ps1 += p2 + p3;
                const int ks = nt >> 1, pos = (nt & 1) * 2;
                pa[ks][pos]     = pack_bf16(p0, p1);
                pa[ks][pos + 1] = pack_bf16(p2, p3);
            }
            ps0 += __shfl_xor_sync(0xffffffffu, ps0, 1);
            ps0 += __shfl_xor_sync(0xffffffffu, ps0, 2);
            ps1 += __shfl_xor_sync(0xffffffffu, ps1, 1);
            ps1 += __shfl_xor_sync(0xffffffffu, ps1, 2);
            srow[0] = srow[0] * al0 + ps0;
            srow[1] = srow[1] * al1 + ps1;
            #pragma unroll
            for (int n = 0; n < 8; n++) {
                Oa[n][0] *= al0; Oa[n][1] *= al0;
                Oa[n][2] *= al1; Oa[n][3] *= al1;
            }
        }

        // O += P V  (P from registers, V via ldmatrix.trans)
        #pragma unroll
        for (int ks = 0; ks < 2; ks++) {
            unsigned vb[4][4];
            const int seqr = kt * 32 + ks * 16 + (lane & 15);
            #pragma unroll
            for (int g = 0; g < 4; g++) {
                const int chv = g * 2 + ach;
                ldsm_x4_t(vb[g], Vb + (uint32_t)seqr * 128 +
                                     (uint32_t)((chv ^ (seqr & 7)) << 4));
            }
            #pragma unroll
            for (int nt = 0; nt < 8; nt++) {
                const int g = nt >> 1, p = nt & 1;
                mma_bf16(Oa[nt], pa[ks], vb[g][p * 2], vb[g][p * 2 + 1]);
            }
        }
    }

    {
        float inv0 = 1.f / srow[0], inv1 = 1.f / srow[1];
        size_t r0 = rowbase + qr0 + gid;
        #pragma unroll
        for (int n = 0; n < 8; n++) {
            int cl = qoff + n * 8 + tig * 2;
            *reinterpret_cast<__nv_bfloat162*>(g_attnb + r0 * CLA_HID + cl) =
                __floats2bfloat162_rn(Oa[n][0] * inv0, Oa[n][1] * inv0);
            *reinterpret_cast<__nv_bfloat162*>(g_attnb + (r0 + 8) * CLA_HID + cl) =
                __floats2bfloat162_rn(Oa[n][2] * inv1, Oa[n][3] * inv1);
        }
    }
}

extern "C" void kernel_launch(void* const* d_in, const int* in_sizes, int n_in,
                              void* d_out, int out_size) {
    const float* x = (const float*)d_in[0];
    const void* lab = d_in[1];
    const float* Wqkv = (const float*)d_in[2];
    const float* bqkv = (const float*)d_in[3];
    const float* Wout = (const float*)d_in[4];
    const float* bout = (const float*)d_in[5];
    float* out = (float*)d_out;

    cudaFuncSetAttribute(attn_k, cudaFuncAttributeMaxDynamicSharedMemorySize,
                         ATTN_SMEM_BYTES);

    __nv_bfloat16* wqkvt; cudaGetSymbolAddress((void**)&wqkvt, g_wqkvt);
    __nv_bfloat16* woutt; cudaGetSymbolAddress((void**)&woutt, g_woutt);

    prep_k<<<PREP_BLOCKS, 256>>>(x, lab, Wqkv, Wout);
    gemm_bf16_k<0><<<dim3(12, 128), 256>>>(wqkvt, bqkv, nullptr, nullptr, CLA_QKVN);
    attn_k<<<512, 512, ATTN_SMEM_BYTES>>>();
    gemm_bf16_k<1><<<dim3(4, 128), 256>>>(woutt, bout, x, out, CLA_HID);
}